// round 17
// baseline (speedup 1.0000x reference)
#include <cuda_runtime.h>
#include <cuda_fp16.h>
#include <cstdint>

// 2-layer LSTM, H=6, F=6, B=4096, T=1024.  Base = R16 (best, 223.6us).
// R17: sigmoid-gate (i,f,o) matvecs in fp16 HFMA2 (2 MACs/lane/pipe-pass vs
// f32x2's 2 passes) -> FMA-pipe work for those gates halves. g-gate (cell
// accumulation path, slope 1) stays f32x2; activations/cell math stay fp32.
// fp16 error control: v-chain and rec-chain accumulated separately (6 terms
// each) and folded in fp32. Operands converted f32x2 -> f16x2 on the fly
// (1 CVT per pair, off the fma pipe).
// Layout: 2 elems/warp, 12 active lanes: lane (l,k) owns hidden k of layer l;
// smem h-exchange (double-buffered slots), no per-step syncwarp (validated),
// tanh.approx acts (sigmoid = 0.5*tanh(z/2)+0.5 folded into weights).

#define WARPS_PER_BLOCK 14
#define THREADS (WARPS_PER_BLOCK * 32)
#define T_LEN 1024
#define TCHUNK 16
#define NCHUNK (T_LEN / TCHUNK)     // 64
#define CSTRIDE 104                 // floats per elem per chunk (96 data + 8 pad)
#define CSTRIDE4 (CSTRIDE / 4)      // 26

typedef unsigned long long ull;

__device__ __forceinline__ float tanha(float x) {
    float y; asm("tanh.approx.f32 %0, %1;" : "=f"(y) : "f"(x)); return y;
}
__device__ __forceinline__ ull pk2(float lo, float hi) {
    ull r; asm("mov.b64 %0, {%1, %2};" : "=l"(r) : "f"(lo), "f"(hi)); return r;
}
__device__ __forceinline__ void upk2(float& lo, float& hi, ull v) {
    asm("mov.b64 {%0, %1}, %2;" : "=f"(lo), "=f"(hi) : "l"(v));
}
__device__ __forceinline__ ull fma2(ull a, ull b, ull c) {
    ull d; asm("fma.rn.f32x2 %0, %1, %2, %3;" : "=l"(d) : "l"(a), "l"(b), "l"(c));
    return d;
}
__device__ __forceinline__ ull mul2(ull a, ull b) {
    ull d; asm("mul.rn.f32x2 %0, %1, %2;" : "=l"(d) : "l"(a), "l"(b));
    return d;
}
__device__ __forceinline__ ull add2(ull a, ull b) {
    ull d; asm("add.rn.f32x2 %0, %1, %2;" : "=l"(d) : "l"(a), "l"(b));
    return d;
}
__device__ __forceinline__ ull lds64(uint32_t addr) {
    ull v; asm volatile("ld.shared.b64 %0, [%1];" : "=l"(v) : "r"(addr));
    return v;
}
__device__ __forceinline__ void sts32(uint32_t addr, float v) {
    asm volatile("st.shared.f32 [%0], %1;" :: "r"(addr), "f"(v) : "memory");
}
// two packed f32 -> one f16x2 (single CVT)
__device__ __forceinline__ __half2 f32p_to_h2(ull v) {
    float lo, hi; upk2(lo, hi, v);
    return __floats2half2_rn(lo, hi);
}

__global__ __launch_bounds__(THREADS, 1)
void lstm2_kernel(const float* __restrict__ x,
                  const float* __restrict__ wih0, const float* __restrict__ whh0,
                  const float* __restrict__ bih0, const float* __restrict__ bhh0,
                  const float* __restrict__ wih1, const float* __restrict__ whh1,
                  const float* __restrict__ bih1, const float* __restrict__ bhh1,
                  float* __restrict__ out, int B)
{
    __shared__ float sx[2][WARPS_PER_BLOCK][2 * CSTRIDE];
    __shared__ float soB[WARPS_PER_BLOCK][2 * CSTRIDE];
    __shared__ float hx[WARPS_PER_BLOCK][96];   // e*48 + slot*20 + l*8 + k

    const int lane = threadIdx.x & 31;
    const int warp = threadIdx.x >> 5;
    const int e    = lane >> 4;
    const int s    = lane & 15;
    const int l    = (s >= 6 && s < 12) ? 1 : 0;
    const int k    = (s < 6) ? s : ((s < 12) ? s - 6 : 0);
    const bool wr  = (s >= 6 && s < 12);

    const int b0 = (blockIdx.x * WARPS_PER_BLOCK + warp) * 2;
    if (b0 >= B) return;

    const float* wih = l ? wih1 : wih0;
    const float* whh = l ? whh1 : whh0;
    const float* bih = l ? bih1 : bih0;
    const float* bhh = l ? bhh1 : bhh0;

    // ---- sigmoid gates (i,f,o): fp16 K-packed weights, 0.5 pre-scale ----
    // sg 0->row k (i), 1->row 6+k (f), 2->row 18+k (o)
    __half2 wxh[3][3], whh_h[3][3], bzh[3];
#pragma unroll
    for (int sg = 0; sg < 3; sg++) {
        const int row = (sg == 0) ? k : ((sg == 1) ? (6 + k) : (18 + k));
#pragma unroll
        for (int p = 0; p < 3; p++) {
            wxh[sg][p]   = __floats2half2_rn(wih[row * 6 + 2 * p] * 0.5f,
                                             wih[row * 6 + 2 * p + 1] * 0.5f);
            whh_h[sg][p] = __floats2half2_rn(whh[row * 6 + 2 * p] * 0.5f,
                                             whh[row * 6 + 2 * p + 1] * 0.5f);
        }
        bzh[sg] = __floats2half2_rn((bih[row] + bhh[row]) * 0.5f, 0.0f);
    }
    // ---- g gate: fp32 f32x2 K-packed ----
    ull wxg[3], whg[3], bzg;
    {
        const int row = 12 + k;
#pragma unroll
        for (int p = 0; p < 3; p++) {
            wxg[p] = pk2(wih[row * 6 + 2 * p], wih[row * 6 + 2 * p + 1]);
            whg[p] = pk2(whh[row * 6 + 2 * p], whh[row * 6 + 2 * p + 1]);
        }
        bzg = pk2(bih[row] + bhh[row], 0.0f);
    }

    // ---- smem addresses ----
    const uint32_t hx_u  = (uint32_t)__cvta_generic_to_shared(&hx[warp][0]);
    const uint32_t hxe_u = hx_u + e * 192;
    const uint32_t recO  = hxe_u + l * 32;
    const uint32_t recE  = recO + 80;
    const uint32_t stO   = hxe_u + ((s < 12) ? (l * 8 + k) * 4 : 56);
    const uint32_t stE   = stO + 80;
    uint32_t sx_u[2];
    sx_u[0] = (uint32_t)__cvta_generic_to_shared(&sx[0][warp][0]);
    sx_u[1] = (uint32_t)__cvta_generic_to_shared(&sx[1][warp][0]);

    hx[warp][lane] = 0.0f; hx[warp][lane + 32] = 0.0f; hx[warp][lane + 64] = 0.0f;
    __syncwarp();

    float cc = 0.0f;

    auto stage = [&](int c, int buf) {
        float4* dst = reinterpret_cast<float4*>(sx[buf][warp]);
#pragma unroll
        for (int i = 0; i < 2; i++) {
            int idx = i * 32 + lane;
            if (idx < 48) {
                int ee  = idx / 24;
                int off = idx - ee * 24;
                const float4* src = reinterpret_cast<const float4*>(
                    x + (size_t)(b0 + ee) * (T_LEN * 6) + c * (TCHUNK * 6));
                dst[ee * CSTRIDE4 + off] = src[off];
            }
        }
    };

    // one step (no per-step sync): ia=input addr, ra=rec addr, wa=h write addr
    auto step = [&](uint32_t ia, uint32_t ra, uint32_t wa, int dt) {
        const ull v0 = lds64(ia), v1 = lds64(ia + 8), v2 = lds64(ia + 16);
        const ull r0 = lds64(ra), r1 = lds64(ra + 8), r2 = lds64(ra + 16);

        // fp16 operands (1 CVT per pair)
        const __half2 hv0 = f32p_to_h2(v0), hv1 = f32p_to_h2(v1), hv2 = f32p_to_h2(v2);
        const __half2 hr0 = f32p_to_h2(r0), hr1 = f32p_to_h2(r1), hr2 = f32p_to_h2(r2);

        // ---- sigmoid gates in fp16: v-chain (bias-seeded) + rec-chain ----
        __half2 zv0 = __hfma2(wxh[0][0], hv0, bzh[0]);
        __half2 zv1 = __hfma2(wxh[1][0], hv0, bzh[1]);
        __half2 zv2 = __hfma2(wxh[2][0], hv0, bzh[2]);
        __half2 zr0 = __hmul2(whh_h[0][0], hr0);
        __half2 zr1 = __hmul2(whh_h[1][0], hr0);
        __half2 zr2 = __hmul2(whh_h[2][0], hr0);
        zv0 = __hfma2(wxh[0][1], hv1, zv0); zv1 = __hfma2(wxh[1][1], hv1, zv1);
        zv2 = __hfma2(wxh[2][1], hv1, zv2);
        zr0 = __hfma2(whh_h[0][1], hr1, zr0); zr1 = __hfma2(whh_h[1][1], hr1, zr1);
        zr2 = __hfma2(whh_h[2][1], hr1, zr2);
        zv0 = __hfma2(wxh[0][2], hv2, zv0); zv1 = __hfma2(wxh[1][2], hv2, zv1);
        zv2 = __hfma2(wxh[2][2], hv2, zv2);
        zr0 = __hfma2(whh_h[0][2], hr2, zr0); zr1 = __hfma2(whh_h[1][2], hr2, zr1);
        zr2 = __hfma2(whh_h[2][2], hr2, zr2);

        // ---- g gate in fp32 (split 3+3) ----
        ull ga = fma2(wxg[0], v0, bzg);
        ull gc = mul2(whg[0], r0);
        ga = fma2(wxg[1], v1, ga);  gc = fma2(whg[1], r1, gc);
        ga = fma2(wxg[2], v2, ga);  gc = fma2(whg[2], r2, gc);

        // ---- folds (fp32) ----
        const float2 av0 = __half22float2(zv0), ar0 = __half22float2(zr0);
        const float2 av1 = __half22float2(zv1), ar1 = __half22float2(zr1);
        const float2 av2 = __half22float2(zv2), ar2 = __half22float2(zr2);
        const float zi = (av0.x + ar0.x) + (av0.y + ar0.y);
        const float zf = (av1.x + ar1.x) + (av1.y + ar1.y);
        const float zo = (av2.x + ar2.x) + (av2.y + ar2.y);
        float gx, gy; upk2(gx, gy, add2(ga, gc));
        const float zg = gx + gy;

        const float gi = fmaf(0.5f, tanha(zi), 0.5f);
        const float gf = fmaf(0.5f, tanha(zf), 0.5f);
        const float gg = tanha(zg);
        const float go = fmaf(0.5f, tanha(zo), 0.5f);

        cc = fmaf(gf, cc, gi * gg);
        const float hn = go * tanha(cc);

        sts32(wa, hn);
        if (dt >= 0 && wr) soB[warp][e * CSTRIDE + dt * 6 + k] = hn;
    };

    // ---- prologue: stage chunk 0; step 0 (layer0 t=0) ----
    stage(0, 0);
    __syncwarp();
    {
        const uint32_t ia = l ? (hxe_u + 0) : (sx_u[0] + e * 416 + 0);
        step(ia, recO, stE, -1);
        if (l) { cc = 0.0f; sts32(stE, 0.0f); }
    }

    // ---- main loop: chunk c covers main steps m = c*16+1 .. c*16+16 ----
    for (int c = 0; c < NCHUNK; c++) {
        if (c + 1 < NCHUNK) stage(c + 1, (c + 1) & 1);
        __syncwarp();

        const uint32_t xb = sx_u[c & 1] + e * 416;
        const uint32_t xn = sx_u[(c + 1) & 1] + e * 416;
        uint32_t inpE = l ? (hxe_u + 80) : (xb + 24);   // even dt: read slot1
        uint32_t inpO = l ? (hxe_u +  0) : (xb + 48);   // odd dt: read slot0
        const uint32_t inpLast = l ? (hxe_u + 0) : xn;  // dt=15 reads next chunk
        const uint32_t sI = l ? 0u : 48u;

#pragma unroll
        for (int dt = 0; dt < TCHUNK; dt += 2) {
            step(inpE, recE, stO, dt);
            const uint32_t ia = (dt + 1 == TCHUNK - 1) ? inpLast : inpO;
            step(ia, recO, stE, dt + 1);
            inpE += sI; inpO += sI;
        }
        __syncwarp();

        // ---- flush h1 outputs for t in [c*16, c*16+16) ----
        {
            const float4* src = reinterpret_cast<const float4*>(soB[warp]);
#pragma unroll
            for (int i = 0; i < 2; i++) {
                int idx = i * 32 + lane;
                if (idx < 48) {
                    int ee  = idx / 24;
                    int off = idx - ee * 24;
                    float4* dst = reinterpret_cast<float4*>(
                        out + (size_t)(b0 + ee) * (T_LEN * 6) + c * (TCHUNK * 6));
                    dst[off] = src[ee * CSTRIDE4 + off];
                }
            }
        }
        __syncwarp();
    }
}

extern "C" void kernel_launch(void* const* d_in, const int* in_sizes, int n_in,
                              void* d_out, int out_size)
{
    const float* x    = (const float*)d_in[0];
    const float* wih0 = (const float*)d_in[1];
    const float* whh0 = (const float*)d_in[2];
    const float* bih0 = (const float*)d_in[3];
    const float* bhh0 = (const float*)d_in[4];
    const float* wih1 = (const float*)d_in[5];
    const float* whh1 = (const float*)d_in[6];
    const float* bih1 = (const float*)d_in[7];
    const float* bhh1 = (const float*)d_in[8];
    float* out = (float*)d_out;

    const int B = in_sizes[0] / (T_LEN * 6);                                 // 4096
    const int grid = (B + 2 * WARPS_PER_BLOCK - 1) / (2 * WARPS_PER_BLOCK);  // 147

    lstm2_kernel<<<grid, THREADS>>>(x, wih0, whh0, bih0, bhh0,
                                    wih1, whh1, bih1, bhh1, out, B);
}